// round 6
// baseline (speedup 1.0000x reference)
#include <cuda_runtime.h>
#include <cstdint>

#define NN 100000
#define NE 1600000
#define CH 64
#define OUTC 32
#define NB_SCAN ((NN + 1023) / 1024)   // 98
#define NR (NE + 3 * NN + 8)           // padded index array capacity

// ---------------- scratch (device globals; no allocation allowed) ----------------
__device__ int   g_deg[NN];
__device__ __align__(16) int g_off[NN];
__device__ int   g_cur[NN];
__device__ float g_dinv[NN];
__device__ int   g_bsums[NB_SCAN];
__device__ __align__(16) int   g_r[NR];         // src row indices, counting-sorted by target, segments 4-padded
__device__ __align__(16) float g_t[NN * CH];    // dinv-scaled transformed features (GEMM out)
__device__ __align__(16) float g_h[NN * CH];    // aggregated + relu

typedef unsigned long long u64;

__device__ __forceinline__ u64 pack2(float lo, float hi) {
    u64 r; asm("mov.b64 %0, {%1, %2};" : "=l"(r) : "f"(lo), "f"(hi)); return r;
}
__device__ __forceinline__ void unpack2(u64 v, float& lo, float& hi) {
    asm("mov.b64 {%0, %1}, %2;" : "=f"(lo), "=f"(hi) : "l"(v));
}
__device__ __forceinline__ void fma2(u64& acc, u64 a, u64 b) {
    asm("fma.rn.f32x2 %0, %1, %2, %0;" : "+l"(acc) : "l"(a), "l"(b));
}

// ---------------- graph preprocessing ----------------
__global__ void k_zero_deg() {
    int i = blockIdx.x * 256 + threadIdx.x;
    if (i < NN / 4) ((int4*)g_deg)[i] = make_int4(0, 0, 0, 0);
}

__global__ void k_count(const int* __restrict__ ei) {
    int e4 = blockIdx.x * 256 + threadIdx.x;
    if (e4 < NE / 4) {
        int4 c = *(const int4*)&ei[NE + e4 * 4];
        atomicAdd(&g_deg[c.x], 1);
        atomicAdd(&g_deg[c.y], 1);
        atomicAdd(&g_deg[c.z], 1);
        atomicAdd(&g_deg[c.w], 1);
    }
}

// per-block exclusive scan of PADDED degrees -> g_off (intra-block), block sums -> g_bsums
__global__ void k_scan1() {
    __shared__ int wsum[32];
    int tid = threadIdx.x;
    int i = blockIdx.x * 1024 + tid;
    int v = (i < NN) ? ((g_deg[i] + 3) & ~3) : 0;
    int lane = tid & 31, wid = tid >> 5;
    int s = v;
#pragma unroll
    for (int d = 1; d < 32; d <<= 1) {
        int n = __shfl_up_sync(0xffffffffu, s, d);
        if (lane >= d) s += n;
    }
    if (lane == 31) wsum[wid] = s;
    __syncthreads();
    if (wid == 0) {
        int t = wsum[lane];
#pragma unroll
        for (int d = 1; d < 32; d <<= 1) {
            int n = __shfl_up_sync(0xffffffffu, t, d);
            if (lane >= d) t += n;
        }
        wsum[lane] = t;
    }
    __syncthreads();
    int warpExcl = (wid > 0) ? wsum[wid - 1] : 0;
    if (i < NN) g_off[i] = warpExcl + (s - v);
    if (tid == 0) g_bsums[blockIdx.x] = wsum[31];
}

// fused: parallel prefix of block sums + finalize offsets + cursors + dinv
__global__ void k_scan23() {
    __shared__ int sb[128];
    int tid = threadIdx.x;
    if (tid < NB_SCAN) sb[tid] = g_bsums[tid];
    __syncthreads();
    int lane = tid & 31;
    int nb = blockIdx.x;
    int partial = 0;
    for (int t = lane; t < nb; t += 32) partial += sb[t];
#pragma unroll
    for (int d = 16; d; d >>= 1) partial += __shfl_xor_sync(0xffffffffu, partial, d);
    int i = blockIdx.x * 1024 + tid;
    if (i < NN) {
        int o = g_off[i] + partial;
        g_off[i] = o;
        g_cur[i] = o;
        g_dinv[i] = rsqrtf((float)(g_deg[i] + 1));
    }
}

__global__ void k_fill(const int* __restrict__ ei) {
    int e4 = blockIdx.x * 256 + threadIdx.x;
    if (e4 < NE / 4) {
        int4 r = *(const int4*)&ei[e4 * 4];
        int4 c = *(const int4*)&ei[NE + e4 * 4];
        g_r[atomicAdd(&g_cur[c.x], 1)] = r.x;
        g_r[atomicAdd(&g_cur[c.y], 1)] = r.y;
        g_r[atomicAdd(&g_cur[c.z], 1)] = r.z;
        g_r[atomicAdd(&g_cur[c.w], 1)] = r.w;
    }
}

// ---------------- GEMM: out[N, COUT] = X[N, 64] @ W[64, COUT] (+bias) (*dinv[row]) ----
// 256 threads; each thread computes 2 rows x 8 cols using packed f32x2 FMA.
template<int COUT, bool BIAS, bool SRC_H, bool DST_PARAM, bool SCALE>
__global__ void k_gemm(const float* __restrict__ Xparam, const float* __restrict__ W,
                       const float* __restrict__ bias, float* __restrict__ outparam) {
    const float* X  = SRC_H ? (const float*)g_h : Xparam;
    float* out      = DST_PARAM ? outparam : (float*)g_t;

    constexpr int G   = COUT / 8;     // column groups per row
    constexpr int TR  = 256 / G;      // thread-rows
    constexpr int RPB = TR * 2;       // rows per block
    constexpr int XS  = 65;
    __shared__ __align__(16) float Wsh[CH * COUT];
    __shared__ float Xsh[RPB][XS];
    int tid = threadIdx.x;

    for (int i = tid; i < CH * COUT; i += 256) Wsh[i] = W[i];

    int row0 = blockIdx.x * RPB;
    {
        int k = tid & 63;
        for (int r = tid >> 6; r < RPB; r += 4) {
            int row = row0 + r;
            Xsh[r][k] = (row < NN) ? X[row * CH + k] : 0.f;
        }
    }
    __syncthreads();

    int cg = tid & (G - 1);
    int rt = tid / G;
    int r0 = rt * 2, r1 = r0 + 1;
    u64 acc0[4] = {0, 0, 0, 0};
    u64 acc1[4] = {0, 0, 0, 0};
    const float* wp = &Wsh[cg * 8];

#pragma unroll 4
    for (int k = 0; k < CH; k++) {
        float x0 = Xsh[r0][k];
        float x1 = Xsh[r1][k];
        u64 xp0 = pack2(x0, x0);
        u64 xp1 = pack2(x1, x1);
        ulonglong2 wa = *(const ulonglong2*)(wp + k * COUT);
        ulonglong2 wb = *(const ulonglong2*)(wp + k * COUT + 4);
        fma2(acc0[0], xp0, wa.x); fma2(acc0[1], xp0, wa.y);
        fma2(acc0[2], xp0, wb.x); fma2(acc0[3], xp0, wb.y);
        fma2(acc1[0], xp1, wa.x); fma2(acc1[1], xp1, wa.y);
        fma2(acc1[2], xp1, wb.x); fma2(acc1[3], xp1, wb.y);
    }

    float4 bb0 = make_float4(0, 0, 0, 0), bb1 = make_float4(0, 0, 0, 0);
    if (BIAS) {
        bb0 = *(const float4*)&bias[cg * 8];
        bb1 = *(const float4*)&bias[cg * 8 + 4];
    }
#pragma unroll
    for (int p = 0; p < 2; p++) {
        int row = row0 + (p == 0 ? r0 : r1);
        if (row < NN) {
            u64* acc = (p == 0) ? acc0 : acc1;
            float4 f0, f1;
            unpack2(acc[0], f0.x, f0.y); unpack2(acc[1], f0.z, f0.w);
            unpack2(acc[2], f1.x, f1.y); unpack2(acc[3], f1.z, f1.w);
            if (SCALE) {
                float s = g_dinv[row];
                f0.x *= s; f0.y *= s; f0.z *= s; f0.w *= s;
                f1.x *= s; f1.y *= s; f1.z *= s; f1.w *= s;
            }
            if (BIAS) {
                f0.x += bb0.x; f0.y += bb0.y; f0.z += bb0.z; f0.w += bb0.w;
                f1.x += bb1.x; f1.y += bb1.y; f1.z += bb1.z; f1.w += bb1.w;
            }
            *(float4*)&out[row * COUT + cg * 8]     = f0;
            *(float4*)&out[row * COUT + cg * 8 + 4] = f1;
        }
    }
}

// ---------------- Aggregation: one warp per node ----------------
// g_h[t] = relu( dinv[t] * (sum_nbr g_t[r] + g_t[t]) + bias )    (g_t rows pre-scaled by dinv[r])
__global__ void k_agg(const float* __restrict__ bias) {
    int gw   = (blockIdx.x * blockDim.x + threadIdx.x) >> 5;
    int lane = threadIdx.x & 31;
    if (gw >= NN) return;

    int start = g_off[gw];          // 4-aligned (padded degrees)
    int cnt   = g_deg[gw];
    const float2* hp = (const float2*)g_t;

    float ax = 0.f, ay = 0.f;
    int endt = start + cnt;
    for (int e = start; e < endt; e += 4) {
        int4 r4 = *(const int4*)&g_r[e];   // warp-uniform broadcast LDG.128
        int rem = endt - e;
        { float2 v = hp[r4.x * 32 + lane]; ax += v.x; ay += v.y; }
        if (rem > 1) { float2 v = hp[r4.y * 32 + lane]; ax += v.x; ay += v.y; }
        if (rem > 2) { float2 v = hp[r4.z * 32 + lane]; ax += v.x; ay += v.y; }
        if (rem > 3) { float2 v = hp[r4.w * 32 + lane]; ax += v.x; ay += v.y; }
    }

    float dt = g_dinv[gw];
    float2 sv = hp[gw * 32 + lane];
    float2 bb = ((const float2*)bias)[lane];
    float ox = fmaf(dt, ax + sv.x, bb.x);
    float oy = fmaf(dt, ay + sv.y, bb.y);
    ((float2*)g_h)[gw * 32 + lane] = make_float2(fmaxf(ox, 0.f), fmaxf(oy, 0.f));
}

// ---------------- launch ----------------
extern "C" void kernel_launch(void* const* d_in, const int* in_sizes, int n_in,
                              void* d_out, int out_size) {
    const float* x    = (const float*)d_in[0];
    const int*   ei   = (const int*)d_in[1];
    const float* W1   = (const float*)d_in[2];
    const float* b1   = (const float*)d_in[3];
    const float* W2   = (const float*)d_in[4];
    const float* b2   = (const float*)d_in[5];
    const float* Wlin = (const float*)d_in[6];
    const float* blin = (const float*)d_in[7];
    float* out = (float*)d_out;

    // CSR build (once per launch; shared by both GCN layers)
    k_zero_deg<<<(NN / 4 + 255) / 256, 256>>>();
    k_count<<<(NE / 4 + 255) / 256, 256>>>(ei);
    k_scan1<<<NB_SCAN, 1024>>>();
    k_scan23<<<NB_SCAN, 1024>>>();
    k_fill<<<(NE / 4 + 255) / 256, 256>>>(ei);

    // layer 1: x -> g_t (scaled) -> g_h
    k_gemm<64, false, false, false, true><<<(NN + 63) / 64, 256>>>(x, W1, nullptr, nullptr);
    k_agg<<<(NN + 7) / 8, 256>>>(b1);
    // layer 2: g_h -> g_t (scaled) -> g_h
    k_gemm<64, false, true, false, true><<<(NN + 63) / 64, 256>>>(nullptr, W2, nullptr, nullptr);
    k_agg<<<(NN + 7) / 8, 256>>>(b2);
    // linear head: g_h -> out
    k_gemm<32, true, true, true, false><<<(NN + 127) / 128, 256>>>(nullptr, Wlin, blin, out);
}

// round 7
// speedup vs baseline: 1.0234x; 1.0234x over previous
#include <cuda_runtime.h>
#include <cuda_fp16.h>
#include <cstdint>

#define NN 100000
#define NE 1600000
#define CH 64
#define OUTC 32
#define NB_SCAN ((NN + 1023) / 1024)   // 98
#define NR (NE + 3 * NN + 16)          // padded index array capacity

// ---------------- scratch (device globals; no allocation allowed) ----------------
__device__ int   g_deg[NN];
__device__ __align__(16) int g_off[NN];
__device__ int   g_cur[NN];
__device__ float g_dinv[NN];
__device__ int   g_bsums[NB_SCAN];              // -1 = unpublished
__device__ __align__(16) int    g_r[NR];        // src rows, counting-sorted by target, segments 4-padded
__device__ __align__(16) __half g_t[NN * CH];   // dinv-scaled transformed features (fp16)
__device__ __align__(16) float  g_h[NN * CH];   // aggregated + relu (fp32)

typedef unsigned long long u64;

__device__ __forceinline__ u64 pack2(float lo, float hi) {
    u64 r; asm("mov.b64 %0, {%1, %2};" : "=l"(r) : "f"(lo), "f"(hi)); return r;
}
__device__ __forceinline__ void unpack2(u64 v, float& lo, float& hi) {
    asm("mov.b64 {%0, %1}, %2;" : "=f"(lo), "=f"(hi) : "l"(v));
}
__device__ __forceinline__ void fma2(u64& acc, u64 a, u64 b) {
    asm("fma.rn.f32x2 %0, %1, %2, %0;" : "+l"(acc) : "l"(a), "l"(b));
}

// ---------------- graph preprocessing ----------------
__global__ void k_zero() {
    int i = blockIdx.x * 256 + threadIdx.x;
    if (i < NN / 4) ((int4*)g_deg)[i] = make_int4(0, 0, 0, 0);
    if (i < NB_SCAN) g_bsums[i] = -1;
}

__global__ void k_count(const int* __restrict__ ei) {
    int e4 = blockIdx.x * 256 + threadIdx.x;
    if (e4 < NE / 4) {
        int4 c = *(const int4*)&ei[NE + e4 * 4];
        atomicAdd(&g_deg[c.x], 1);
        atomicAdd(&g_deg[c.y], 1);
        atomicAdd(&g_deg[c.z], 1);
        atomicAdd(&g_deg[c.w], 1);
    }
}

// Fused single-pass scan: per-block scan of padded degrees + decoupled lookback
// over block sums + finalize offsets/cursors/dinv.
__global__ void k_scan() {
    __shared__ int wsum[32];
    __shared__ int base_sh;
    int tid = threadIdx.x;
    int b   = blockIdx.x;
    int i   = b * 1024 + tid;
    int deg = (i < NN) ? g_deg[i] : 0;
    int v   = (deg + 3) & ~3;                 // 4-padded segment length
    int lane = tid & 31, wid = tid >> 5;
    int s = v;
#pragma unroll
    for (int d = 1; d < 32; d <<= 1) {
        int n = __shfl_up_sync(0xffffffffu, s, d);
        if (lane >= d) s += n;
    }
    if (lane == 31) wsum[wid] = s;
    __syncthreads();
    if (wid == 0) {
        int t = wsum[lane];
#pragma unroll
        for (int d = 1; d < 32; d <<= 1) {
            int n = __shfl_up_sync(0xffffffffu, t, d);
            if (lane >= d) t += n;
        }
        wsum[lane] = t;                        // inclusive warp-total scan
    }
    __syncthreads();
    // publish this block's total, then look back over all previous blocks
    if (tid == 0) atomicExch(&g_bsums[b], wsum[31]);
    if (tid < 32) {
        int sum = 0;
        for (int j = tid; j < b; j += 32) {
            int t;
            do { t = atomicAdd(&g_bsums[j], 0); } while (t < 0);
            sum += t;
        }
#pragma unroll
        for (int d = 16; d; d >>= 1) sum += __shfl_xor_sync(0xffffffffu, sum, d);
        if (tid == 0) base_sh = sum;
    }
    __syncthreads();
    if (i < NN) {
        int warpExcl = (wid > 0) ? wsum[wid - 1] : 0;
        int o = base_sh + warpExcl + (s - v);
        g_off[i] = o;
        g_cur[i] = o;
        g_dinv[i] = rsqrtf((float)(deg + 1));
    }
}

__global__ void k_fill(const int* __restrict__ ei) {
    int e4 = blockIdx.x * 256 + threadIdx.x;
    if (e4 < NE / 4) {
        int4 r = *(const int4*)&ei[e4 * 4];
        int4 c = *(const int4*)&ei[NE + e4 * 4];
        g_r[atomicAdd(&g_cur[c.x], 1)] = r.x;
        g_r[atomicAdd(&g_cur[c.y], 1)] = r.y;
        g_r[atomicAdd(&g_cur[c.z], 1)] = r.z;
        g_r[atomicAdd(&g_cur[c.w], 1)] = r.w;
    }
}

// ---------------- GEMM: out[N, COUT] = X[N, 64] @ W[64, COUT] (+bias) (*dinv[row]) ----
// 256 threads; each thread computes 2 rows x 8 cols using packed f32x2 FMA.
// DST_PARAM=false -> write fp16 to g_t; true -> write fp32 to outparam.
template<int COUT, bool BIAS, bool SRC_H, bool DST_PARAM, bool SCALE>
__global__ void k_gemm(const float* __restrict__ Xparam, const float* __restrict__ W,
                       const float* __restrict__ bias, float* __restrict__ outparam) {
    const float* X = SRC_H ? (const float*)g_h : Xparam;

    constexpr int G   = COUT / 8;     // column groups per row
    constexpr int TR  = 256 / G;      // thread-rows
    constexpr int RPB = TR * 2;       // rows per block
    constexpr int XS  = 65;
    __shared__ __align__(16) float Wsh[CH * COUT];
    __shared__ float Xsh[RPB][XS];
    int tid = threadIdx.x;

    for (int i = tid; i < CH * COUT; i += 256) Wsh[i] = W[i];

    int row0 = blockIdx.x * RPB;
    {
        int k = tid & 63;
        for (int r = tid >> 6; r < RPB; r += 4) {
            int row = row0 + r;
            Xsh[r][k] = (row < NN) ? X[row * CH + k] : 0.f;
        }
    }
    __syncthreads();

    int cg = tid & (G - 1);
    int rt = tid / G;
    int r0 = rt * 2, r1 = r0 + 1;
    u64 acc0[4] = {0, 0, 0, 0};
    u64 acc1[4] = {0, 0, 0, 0};
    const float* wp = &Wsh[cg * 8];

#pragma unroll 4
    for (int k = 0; k < CH; k++) {
        float x0 = Xsh[r0][k];
        float x1 = Xsh[r1][k];
        u64 xp0 = pack2(x0, x0);
        u64 xp1 = pack2(x1, x1);
        ulonglong2 wa = *(const ulonglong2*)(wp + k * COUT);
        ulonglong2 wb = *(const ulonglong2*)(wp + k * COUT + 4);
        fma2(acc0[0], xp0, wa.x); fma2(acc0[1], xp0, wa.y);
        fma2(acc0[2], xp0, wb.x); fma2(acc0[3], xp0, wb.y);
        fma2(acc1[0], xp1, wa.x); fma2(acc1[1], xp1, wa.y);
        fma2(acc1[2], xp1, wb.x); fma2(acc1[3], xp1, wb.y);
    }

    float4 bb0 = make_float4(0, 0, 0, 0), bb1 = make_float4(0, 0, 0, 0);
    if (BIAS) {
        bb0 = *(const float4*)&bias[cg * 8];
        bb1 = *(const float4*)&bias[cg * 8 + 4];
    }
#pragma unroll
    for (int p = 0; p < 2; p++) {
        int row = row0 + (p == 0 ? r0 : r1);
        if (row < NN) {
            u64* acc = (p == 0) ? acc0 : acc1;
            float4 f0, f1;
            unpack2(acc[0], f0.x, f0.y); unpack2(acc[1], f0.z, f0.w);
            unpack2(acc[2], f1.x, f1.y); unpack2(acc[3], f1.z, f1.w);
            if (SCALE) {
                float s = g_dinv[row];
                f0.x *= s; f0.y *= s; f0.z *= s; f0.w *= s;
                f1.x *= s; f1.y *= s; f1.z *= s; f1.w *= s;
            }
            if (BIAS) {
                f0.x += bb0.x; f0.y += bb0.y; f0.z += bb0.z; f0.w += bb0.w;
                f1.x += bb1.x; f1.y += bb1.y; f1.z += bb1.z; f1.w += bb1.w;
            }
            if (DST_PARAM) {
                *(float4*)&outparam[row * COUT + cg * 8]     = f0;
                *(float4*)&outparam[row * COUT + cg * 8 + 4] = f1;
            } else {
                __half2 hv[4];
                hv[0] = __floats2half2_rn(f0.x, f0.y);
                hv[1] = __floats2half2_rn(f0.z, f0.w);
                hv[2] = __floats2half2_rn(f1.x, f1.y);
                hv[3] = __floats2half2_rn(f1.z, f1.w);
                *(uint4*)&g_t[row * COUT + cg * 8] = *(uint4*)hv;
            }
        }
    }
}

// ---------------- Aggregation: one warp per node, fp16 gathers, fp32 accum ----------
// g_h[t] = relu( dinv[t] * (sum_nbr g_t[r] + g_t[t]) + bias )   (g_t pre-scaled by dinv[r])
__global__ void k_agg(const float* __restrict__ bias) {
    int gw   = (blockIdx.x * blockDim.x + threadIdx.x) >> 5;
    int lane = threadIdx.x & 31;
    if (gw >= NN) return;

    int start = g_off[gw];          // 4-aligned (padded degrees)
    int cnt   = g_deg[gw];
    const __half2* hp = (const __half2*)g_t;

    float ax = 0.f, ay = 0.f;
    int endt = start + cnt;
    for (int e = start; e < endt; e += 8) {
        int4 a = *(const int4*)&g_r[e];       // warp-uniform broadcast LDG.128
        int4 b = *(const int4*)&g_r[e + 4];   // (slack-padded; predicated use)
        int rem = endt - e;
        {            float2 v = __half22float2(hp[a.x * 32 + lane]); ax += v.x; ay += v.y; }
        if (rem > 1) { float2 v = __half22float2(hp[a.y * 32 + lane]); ax += v.x; ay += v.y; }
        if (rem > 2) { float2 v = __half22float2(hp[a.z * 32 + lane]); ax += v.x; ay += v.y; }
        if (rem > 3) { float2 v = __half22float2(hp[a.w * 32 + lane]); ax += v.x; ay += v.y; }
        if (rem > 4) { float2 v = __half22float2(hp[b.x * 32 + lane]); ax += v.x; ay += v.y; }
        if (rem > 5) { float2 v = __half22float2(hp[b.y * 32 + lane]); ax += v.x; ay += v.y; }
        if (rem > 6) { float2 v = __half22float2(hp[b.z * 32 + lane]); ax += v.x; ay += v.y; }
        if (rem > 7) { float2 v = __half22float2(hp[b.w * 32 + lane]); ax += v.x; ay += v.y; }
    }

    float dt = g_dinv[gw];
    float2 sv = __half22float2(hp[gw * 32 + lane]);
    float2 bb = ((const float2*)bias)[lane];
    float ox = fmaf(dt, ax + sv.x, bb.x);
    float oy = fmaf(dt, ay + sv.y, bb.y);
    ((float2*)g_h)[gw * 32 + lane] = make_float2(fmaxf(ox, 0.f), fmaxf(oy, 0.f));
}

// ---------------- launch ----------------
extern "C" void kernel_launch(void* const* d_in, const int* in_sizes, int n_in,
                              void* d_out, int out_size) {
    const float* x    = (const float*)d_in[0];
    const int*   ei   = (const int*)d_in[1];
    const float* W1   = (const float*)d_in[2];
    const float* b1   = (const float*)d_in[3];
    const float* W2   = (const float*)d_in[4];
    const float* b2   = (const float*)d_in[5];
    const float* Wlin = (const float*)d_in[6];
    const float* blin = (const float*)d_in[7];
    float* out = (float*)d_out;

    // CSR build (once per launch; shared by both GCN layers)
    k_zero<<<(NN / 4 + 255) / 256, 256>>>();
    k_count<<<(NE / 4 + 255) / 256, 256>>>(ei);
    k_scan<<<NB_SCAN, 1024>>>();
    k_fill<<<(NE / 4 + 255) / 256, 256>>>(ei);   // <- profile slot 4

    // layer 1: x -> g_t (fp16, scaled) -> g_h
    k_gemm<64, false, false, false, true><<<(NN + 63) / 64, 256>>>(x, W1, nullptr, nullptr);
    k_agg<<<(NN + 7) / 8, 256>>>(b1);
    // layer 2: g_h -> g_t (fp16, scaled) -> g_h
    k_gemm<64, false, true, false, true><<<(NN + 63) / 64, 256>>>(nullptr, W2, nullptr, nullptr);
    k_agg<<<(NN + 7) / 8, 256>>>(b2);
    // linear head: g_h -> out (fp32)
    k_gemm<32, true, true, true, false><<<(NN + 127) / 128, 256>>>(nullptr, Wlin, blin, out);
}